// round 10
// baseline (speedup 1.0000x reference)
#include <cuda_runtime.h>
#include <cstdint>

#define BB 32
#define JJ 256
#define MM 128
#define DD 200
#define NTH 512
#define CH 50            // d-chunk per rank
#define CSZ 4            // cluster size
#define MP 53            // padded mem chunk row stride

// ---------------- persistent transposed weight scratch (fp32) ----------------
__device__ __align__(16) float g_wTg[400 * 800];   // [k][4*d+g], k<200 ih else hh
__device__ __align__(16) float g_wTfc1[400 * 200]; // [k][d], k: x then q
__device__ __align__(16) float g_wTfc[200 * 200];  // [k][d]
__device__ __align__(16) float g_bg[800];          // b_ih+b_hh gate-interleaved

__global__ void prep_kernel(const float* __restrict__ w_fc, const float* __restrict__ w_fc1,
                            const float* __restrict__ w_ih, const float* __restrict__ w_hh,
                            const float* __restrict__ b_ih, const float* __restrict__ b_hh)
{
    int stride = gridDim.x * blockDim.x;
    int i0 = blockIdx.x * blockDim.x + threadIdx.x;

    for (int idx = i0; idx < 400 * 800; idx += stride) {
        int k = idx / 800, rem = idx % 800;
        int d = rem >> 2, g = rem & 3;
        int o = g * 200 + d;
        g_wTg[idx] = (k < 200) ? w_ih[o * 200 + k] : w_hh[o * 200 + (k - 200)];
    }
    for (int idx = i0; idx < 800; idx += stride) {
        int d = idx >> 2, g = idx & 3;
        int o = g * 200 + d;
        g_bg[idx] = b_ih[o] + b_hh[o];
    }
    for (int idx = i0; idx < 400 * 200; idx += stride) {
        int k = idx / 200, d = idx % 200;
        g_wTfc1[idx] = w_fc1[d * 400 + k];
    }
    for (int idx = i0; idx < 200 * 200; idx += stride) {
        int k = idx / 200, d = idx % 200;
        g_wTfc[idx] = w_fc[d * 200 + k];
    }
}

__device__ __forceinline__ float sigf(float v) { return 1.0f / (1.0f + __expf(-v)); }
__device__ __forceinline__ float ftanh(float x) { return 1.0f - 2.0f / (__expf(2.0f * x) + 1.0f); }

__device__ __forceinline__ void cluster_bar()
{
    asm volatile("barrier.cluster.arrive.aligned;\n\t"
                 "barrier.cluster.wait.aligned;" ::: "memory");
}
__device__ __forceinline__ void cluster_arrive()
{
    asm volatile("barrier.cluster.arrive.aligned;" ::: "memory");
}
__device__ __forceinline__ void cluster_wait()
{
    asm volatile("barrier.cluster.wait.aligned;" ::: "memory");
}
__device__ __forceinline__ void st_peer(uint32_t laddr, uint32_t peer, float v)
{
    uint32_t r;
    asm volatile("mapa.shared::cluster.u32 %0, %1, %2;" : "=r"(r) : "r"(laddr), "r"(peer));
    asm volatile("st.shared::cluster.f32 [%0], %1;" :: "r"(r), "f"(v) : "memory");
}
__device__ __forceinline__ void st_peer_v4(uint32_t laddr, uint32_t peer, float4 v)
{
    uint32_t r;
    unsigned long long lo = (unsigned long long)__float_as_uint(v.x) |
                            ((unsigned long long)__float_as_uint(v.y) << 32);
    unsigned long long hi = (unsigned long long)__float_as_uint(v.z) |
                            ((unsigned long long)__float_as_uint(v.w) << 32);
    asm volatile("mapa.shared::cluster.u32 %0, %1, %2;" : "=r"(r) : "r"(laddr), "r"(peer));
    asm volatile("st.shared::cluster.b64 [%0], %1;" :: "r"(r), "l"(lo) : "memory");
    asm volatile("st.shared::cluster.b64 [%0+8], %1;" :: "r"(r), "l"(hi) : "memory");
}

// ---------------- SMEM layout (float indices) ----------------
#define SM_MEM   0       // mem[2 bank][128][53] = 13568
#define SM_GP    13568   // gparts[4 src][200] = 800
#define SM_ATTP  14368   // attp[4 src][128] = 512
#define SM_QP    14880   // qparts[4][50] = 200
#define SM_ZP    15080   // zparts[4][50] = 200
#define SM_PG    15280   // partG: gates q-half (2ks x 200 float4) = 1600; aliases att/x partials
#define SM_PH    16880   // partH: gates h-half (2ks x 200 float4) = 1600
#define SM_PF    18480   // partF: fc1 partials 4x200 = 800
#define SM_PZ    19280   // partZ: z sv-half [0..400) + q-half [400..800)
#define SM_PB    20080   // partB: P1 scratch (qinit 400 + hinit 100) = 512
#define SM_ATT   20592   // att[128]
#define SM_RED   20720   // red[8]
#define SM_XV    20728   // xv[56]
#define SM_CS    20784   // cstage[2][128] = 256
#define SM_BJ    21040   // bstage[2][200] = 400
#define SM_QL    21440   // qloc[56]
#define SM_HL    21496   // hloc[56]
#define SM_CV    21552   // cvec[56]
#define SM_BG    21608   // bgs[224]
#define SM_BFC   21832   // bfcs[56]
#define SM_BFC1  21888   // bfc1s[56]
#define SM_WFC1  21944   // wfc1 slice [100 rows][200] = 20000
#define SM_WZ    41944   // z-fc slice [50 rows][200] = 10000
#define SM_TOT   51944   // 207776 bytes

__global__ void __launch_bounds__(NTH, 1) __cluster_dims__(CSZ, 1, 1)
speaker_kernel(const float* __restrict__ cosp, const float* __restrict__ bank,
               const float* __restrict__ mem_a, const float* __restrict__ mem_b,
               const float* __restrict__ b_fc, const float* __restrict__ b_fc1,
               float* __restrict__ out)
{
    extern __shared__ float sm[];
    float* gparts = sm + SM_GP;
    float* attp   = sm + SM_ATTP;
    float* qparts = sm + SM_QP;
    float* zparts = sm + SM_ZP;
    float* att    = sm + SM_ATT;
    float* red    = sm + SM_RED;
    float* xv     = sm + SM_XV;
    float* qloc   = sm + SM_QL;
    float* hloc   = sm + SM_HL;
    float* cvec   = sm + SM_CV;
    float* bgs    = sm + SM_BG;
    float* bfcs   = sm + SM_BFC;
    float* bfc1s  = sm + SM_BFC1;
    float* wfc1s  = sm + SM_WFC1;
    float* wzs    = sm + SM_WZ;

    const int tid  = threadIdx.x;
    const int lane = blockIdx.x >> 2;
    const uint32_t rank = blockIdx.x & 3;
    const int cbase = (int)rank * CH;
    const uint32_t sb = (uint32_t)__cvta_generic_to_shared(sm);

    // ---- init ----
    if (tid < 224) bgs[tid] = g_bg[rank * 200 + min(tid, 199)];
    if (tid < CH) { bfcs[tid] = b_fc[cbase + tid]; bfc1s[tid] = b_fc1[cbase + tid]; }
    for (int idx = tid; idx < MM * CH; idx += NTH) {
        int m = idx / CH, d = idx % CH;
        sm[SM_MEM + m * MP + d]           = mem_a[lane * MM * DD + m * DD + cbase + d];
        sm[SM_MEM + MM * MP + m * MP + d] = mem_b[lane * MM * DD + m * DD + cbase + d];
    }
    for (int idx = tid; idx < 20000; idx += NTH) {
        int rr = idx / 200, c = idx % 200;
        int grow = (rr < 50) ? (cbase + rr) : (200 + cbase + rr - 50);
        wfc1s[idx] = g_wTfc1[grow * 200 + c];
    }
    for (int idx = tid; idx < 10000; idx += NTH) {
        int rr = idx / 200, c = idx % 200;
        wzs[idx] = g_wTfc[(cbase + rr) * 200 + c];
    }
    if (tid < MM) sm[SM_CS + tid] = cosp[(lane * JJ + 0) * MM + tid];
    if (tid < DD) sm[SM_BJ + tid] = bank[(0 * BB + lane) * DD + tid];
    __syncthreads();
    cluster_bar();

    // ---- P1(0): q-init + h-init into partB ----
    {
        const float* bjj = sm + SM_BJ;      // buf 0
        const float* csj = sm + SM_CS;
        if (tid < 400) {
            int ks = tid / 50, c = tid % 50;
            int k0 = ks * 25;
            const float* W = g_wTfc + cbase + c;
            float a = 0.f;
            #pragma unroll 5
            for (int i = 0; i < 25; ++i) a += bjj[k0 + i] * W[(k0 + i) * 200];
            sm[SM_PB + ks * 50 + c] = a;
        } else if (tid < 500) {
            int t = tid - 400, seg = t / 50, d = t % 50;
            const float* mp = sm + SM_MEM + (seg * 64) * MP + d;   // bank 0
            float a = 0.f;
            #pragma unroll 8
            for (int m = 0; m < 64; ++m) a += csj[seg * 64 + m] * mp[m * MP];
            sm[SM_PB + 400 + seg * 50 + d] = a;
        }
    }
    __syncthreads();
    // ---- P2(0) ----
    if (tid >= 64 && tid < 114) {
        int t = tid - 64;
        float a = bfcs[t];
        #pragma unroll
        for (int ks = 0; ks < 8; ++ks) a += sm[SM_PB + ks * 50 + t];
        qloc[t] = a;
        cvec[t] = 0.0f;
    } else if (tid >= 128 && tid < 178) {
        int t = tid - 128;
        hloc[t] = sm[SM_PB + 400 + t] + sm[SM_PB + 450 + t];
    }
    __syncthreads();

    for (int j = 0; j < JJ; ++j) {
        const int flag = j & 1;
        const int slot = j >> 1;
        float* mem = sm + SM_MEM + flag * (MM * MP);

        // ---------------- inner loop P=3 ----------------
        for (int p = 0; p < 3; ++p) {
            // G0: gates q-half (p>0) or full (p==0); prefetch next stage at p==0
            if (tid < 400) {
                int ks = tid / 200, cp = tid % 200;
                const float* actq = qloc + ks * 25;
                const float4* Wq = reinterpret_cast<const float4*>(g_wTg)
                                   + (cbase + ks * 25) * 200 + cp;
                float4 sq = make_float4(0.f, 0.f, 0.f, 0.f);
                if (p == 0) {
                    const float* acth = hloc + ks * 25;
                    const float4* Wh = reinterpret_cast<const float4*>(g_wTg)
                                       + (200 + cbase + ks * 25) * 200 + cp;
                    float4 sh = make_float4(0.f, 0.f, 0.f, 0.f);
                    #pragma unroll 5
                    for (int i = 0; i < 25; ++i) {
                        float vq = actq[i], vh = acth[i];
                        float4 wq = Wq[i * 200], wh = Wh[i * 200];
                        sq.x += vq * wq.x; sq.y += vq * wq.y; sq.z += vq * wq.z; sq.w += vq * wq.w;
                        sh.x += vh * wh.x; sh.y += vh * wh.y; sh.z += vh * wh.z; sh.w += vh * wh.w;
                    }
                    reinterpret_cast<float4*>(sm + SM_PH)[ks * 200 + cp] = sh;
                } else {
                    #pragma unroll 5
                    for (int i = 0; i < 25; ++i) {
                        float vq = actq[i];
                        float4 wq = Wq[i * 200];
                        sq.x += vq * wq.x; sq.y += vq * wq.y; sq.z += vq * wq.z; sq.w += vq * wq.w;
                    }
                }
                reinterpret_cast<float4*>(sm + SM_PG)[ks * 200 + cp] = sq;
            } else if (p == 0 && j + 1 < JJ) {
                int nj = j + 1, nb = nj & 1, t = tid - 400;
                for (int i = t; i < MM; i += 112)
                    sm[SM_CS + nb * 128 + i] = cosp[(lane * JJ + nj) * MM + i];
                for (int i = t; i < DD; i += 112)
                    sm[SM_BJ + nb * 200 + i] = bank[(nj * BB + lane) * DD + i];
            }
            __syncthreads();
            // G0b: combine q-half + h-half, deposit gate-quad to owner
            if (tid < 200) {
                const float4* g4 = reinterpret_cast<const float4*>(sm + SM_PG);
                const float4* h4 = reinterpret_cast<const float4*>(sm + SM_PH);
                float4 a = g4[tid], b = g4[200 + tid], c4 = h4[tid], d4 = h4[200 + tid];
                float4 v = make_float4(a.x + b.x + c4.x + d4.x,
                                       a.y + b.y + c4.y + d4.y,
                                       a.z + b.z + c4.z + d4.z,
                                       a.w + b.w + c4.w + d4.w);
                int owner = tid / CH, cq = tid % CH;
                uint32_t off = SM_GP + rank * 200 + cq * 4;
                if (owner == (int)rank) *reinterpret_cast<float4*>(sm + off) = v;
                else st_peer_v4(sb + 4u * off, (uint32_t)owner, v);
            }
            cluster_arrive();                    // Bg
            // [Bg gap] FQ: fc1 q-half (uses q(p-1), final)
            if (tid < 400) {
                int ks = tid / 200, cp = tid % 200;
                const float* act = qloc + ks * 25;
                const float* W = wfc1s + ((2 + ks) * 25) * 200 + cp;
                float a = 0.f;
                #pragma unroll 5
                for (int i = 0; i < 25; ++i) a += act[i] * W[i * 200];
                sm[SM_PF + (2 + ks) * 200 + cp] = a;
            }
            __syncthreads();
            cluster_wait();                      // Bg done
            // G1: reduce 4 gate sources + LSTM
            if (tid < 224) {
                int t = min(tid, 199);
                int chl = t >> 2, gi = t & 3;
                float g = bgs[t];
                #pragma unroll
                for (int s = 0; s < 4; ++s) g += gparts[s * 200 + chl * 4 + gi];
                float val = (gi == 2) ? ftanh(g) : sigf(g);
                float ig = __shfl_sync(0xffffffffu, val, 0, 4);
                float fg = __shfl_sync(0xffffffffu, val, 1, 4);
                float gg = __shfl_sync(0xffffffffu, val, 2, 4);
                float og = __shfl_sync(0xffffffffu, val, 3, 4);
                if (tid < 200 && gi == 0) {
                    float cc = fg * cvec[chl] + ig * gg;
                    cvec[chl] = cc;
                    hloc[chl] = og * ftanh(cc);
                }
            }
            __syncthreads();
            // G2: attention logit partials (into partG alias)
            if (tid < 256) {
                int m = tid & 127, hf = tid >> 7;
                float a = 0.f;
                const float* mrow = mem + m * MP + hf * 25;
                const float* hseg = hloc + hf * 25;
                #pragma unroll 5
                for (int i = 0; i < 25; ++i) a += hseg[i] * mrow[i];
                sm[SM_PG + hf * 128 + m] = a;
            }
            __syncthreads();
            // G2b: push logit partials to peers
            if (tid < 128) {
                float a = sm[SM_PG + tid] + sm[SM_PG + 128 + tid];
                uint32_t off = SM_ATTP + rank * 128 + tid;
                sm[off] = a;
                #pragma unroll
                for (uint32_t pr = 1; pr < CSZ; ++pr)
                    st_peer(sb + 4u * off, (rank + pr) & 3, a);
            }
            cluster_arrive();                    // Ba
            // [Ba gap] HH: gates h-half for p+1 (p<2) | z sv-half (p==2)
            if (tid < 400) {
                int ks = tid / 200, cp = tid % 200;
                if (p < 2) {
                    const float* acth = hloc + ks * 25;
                    const float4* Wh = reinterpret_cast<const float4*>(g_wTg)
                                       + (200 + cbase + ks * 25) * 200 + cp;
                    float4 sh = make_float4(0.f, 0.f, 0.f, 0.f);
                    #pragma unroll 5
                    for (int i = 0; i < 25; ++i) {
                        float vh = acth[i];
                        float4 wh = Wh[i * 200];
                        sh.x += vh * wh.x; sh.y += vh * wh.y; sh.z += vh * wh.z; sh.w += vh * wh.w;
                    }
                    reinterpret_cast<float4*>(sm + SM_PH)[ks * 200 + cp] = sh;
                } else {
                    const float* svp = mem + slot * MP + ks * 25;
                    const float* W = wzs + (ks * 25) * 200 + cp;
                    float a = 0.f;
                    #pragma unroll 5
                    for (int i = 0; i < 25; ++i) a += svp[i] * W[i * 200];
                    sm[SM_PZ + ks * 200 + cp] = a;
                }
            }
            __syncthreads();
            cluster_wait();                      // Ba done
            // G3: fused single-warp softmax
            if (tid < 32) {
                float v0 = attp[tid]      + attp[128 + tid] + attp[256 + tid] + attp[384 + tid];
                float v1 = attp[32 + tid] + attp[160 + tid] + attp[288 + tid] + attp[416 + tid];
                float v2 = attp[64 + tid] + attp[192 + tid] + attp[320 + tid] + attp[448 + tid];
                float v3 = attp[96 + tid] + attp[224 + tid] + attp[352 + tid] + attp[480 + tid];
                float mx = fmaxf(fmaxf(v0, v1), fmaxf(v2, v3));
                #pragma unroll
                for (int o = 16; o > 0; o >>= 1) mx = fmaxf(mx, __shfl_xor_sync(0xffffffffu, mx, o));
                float e0 = __expf(v0 - mx), e1 = __expf(v1 - mx);
                float e2 = __expf(v2 - mx), e3 = __expf(v3 - mx);
                float s = e0 + e1 + e2 + e3;
                #pragma unroll
                for (int o = 16; o > 0; o >>= 1) s += __shfl_xor_sync(0xffffffffu, s, o);
                att[tid] = e0; att[32 + tid] = e1; att[64 + tid] = e2; att[96 + tid] = e3;
                if (tid == 0) red[0] = 1.0f / s;
            }
            __syncthreads();
            // G5: x chunk partials (into partG alias)
            if (tid < 400) {
                int seg = tid / 50, d = tid % 50;
                float a = 0.f;
                const float* mp = mem + (seg * 16) * MP + d;
                #pragma unroll 8
                for (int m = 0; m < 16; ++m) a += att[seg * 16 + m] * mp[m * MP];
                sm[SM_PG + seg * 50 + d] = a;
            }
            __syncthreads();
            if (tid < CH) {
                float a = 0.f;
                #pragma unroll
                for (int s = 0; s < 8; ++s) a += sm[SM_PG + s * 50 + tid];
                xv[tid] = a * red[0];
            }
            __syncthreads();
            // G6: fc1 x-half
            if (tid < 400) {
                int ks = tid / 200, cp = tid % 200;
                const float* act = xv + ks * 25;
                const float* W = wfc1s + (ks * 25) * 200 + cp;
                float a = 0.f;
                #pragma unroll 5
                for (int i = 0; i < 25; ++i) a += act[i] * W[i * 200];
                sm[SM_PF + ks * 200 + cp] = a;
            }
            __syncthreads();
            // G6b: combine 4 fc1 partials + deposit to owner
            if (tid < 200) {
                float v = sm[SM_PF + tid] + sm[SM_PF + 200 + tid]
                        + sm[SM_PF + 400 + tid] + sm[SM_PF + 600 + tid];
                int owner = tid / CH;
                uint32_t off = SM_QP + rank * CH + (tid % CH);
                if (owner == (int)rank) sm[off] = v;
                else st_peer(sb + 4u * off, (uint32_t)owner, v);
            }
            cluster_bar();                       // Bq (no gap work available)
            // G7: q chunk reduce
            if (tid < CH) {
                float a = bfc1s[tid];
                #pragma unroll
                for (int s = 0; s < 4; ++s) a += qparts[s * CH + tid];
                qloc[tid] = a;
            }
            __syncthreads();
        }

        // ---- epilogue ----
        // ZQ: z q-half + out write
        if (tid < 400) {
            int ks = tid / 200, cp = tid % 200;
            const float* qp = qloc + ks * 25;
            const float* W = wzs + (ks * 25) * 200 + cp;
            float a = 0.f;
            #pragma unroll 5
            for (int i = 0; i < 25; ++i) a += qp[i] * W[i * 200];
            sm[SM_PZ + 400 + ks * 200 + cp] = a;
        } else if (tid >= 448 && tid < 448 + CH) {
            int t = tid - 448;
            out[(lane * JJ + j) * DD + cbase + t] = qloc[t];
        }
        __syncthreads();
        // ZD: combine sv-half + q-half, deposit to owner
        if (tid < 200) {
            float v = sm[SM_PZ + tid] + sm[SM_PZ + 200 + tid]
                    + sm[SM_PZ + 400 + tid] + sm[SM_PZ + 600 + tid];
            int owner = tid / CH;
            uint32_t off = SM_ZP + rank * CH + (tid % CH);
            if (owner == (int)rank) sm[off] = v;
            else st_peer(sb + 4u * off, (uint32_t)owner, v);
        }
        cluster_arrive();                        // Bz
        // [Bz gap] P1(j+1): q-init + h-init (reads bank flag(j+1), untouched this step)
        if (j + 1 < JJ) {
            int jb2 = (j + 1) & 1;
            const float* bjj = sm + SM_BJ + jb2 * 200;
            const float* csj = sm + SM_CS + jb2 * 128;
            const float* memn = sm + SM_MEM + jb2 * (MM * MP);
            if (tid < 400) {
                int ks = tid / 50, c = tid % 50;
                int k0 = ks * 25;
                const float* W = g_wTfc + cbase + c;
                float a = 0.f;
                #pragma unroll 5
                for (int i = 0; i < 25; ++i) a += bjj[k0 + i] * W[(k0 + i) * 200];
                sm[SM_PB + ks * 50 + c] = a;
            } else if (tid < 500) {
                int t = tid - 400, seg = t / 50, d = t % 50;
                const float* mp = memn + (seg * 64) * MP + d;
                float a = 0.f;
                #pragma unroll 8
                for (int m = 0; m < 64; ++m) a += csj[seg * 64 + m] * mp[m * MP];
                sm[SM_PB + 400 + seg * 50 + d] = a;
            }
        }
        __syncthreads();
        cluster_wait();                          // Bz done
        // z-reduce + mem update ; P2(j+1) combine
        if (tid < CH) {
            float a = 2.0f * bfcs[tid];
            #pragma unroll
            for (int s = 0; s < 4; ++s) a += zparts[s * CH + tid];
            float z = tanhf(a);
            mem[slot * MP + tid] *= z;
        } else if (j + 1 < JJ && tid >= 64 && tid < 114) {
            int t = tid - 64;
            float a = bfcs[t];
            #pragma unroll
            for (int ks = 0; ks < 8; ++ks) a += sm[SM_PB + ks * 50 + t];
            qloc[t] = a;
            cvec[t] = 0.0f;
        } else if (j + 1 < JJ && tid >= 128 && tid < 178) {
            int t = tid - 128;
            hloc[t] = sm[SM_PB + 400 + t] + sm[SM_PB + 450 + t];
        }
        __syncthreads();
    }
}

extern "C" void kernel_launch(void* const* d_in, const int* in_sizes, int n_in,
                              void* d_out, int out_size)
{
    const float* cosp  = (const float*)d_in[0];
    const float* bank  = (const float*)d_in[1];
    const float* mem_a = (const float*)d_in[2];
    const float* mem_b = (const float*)d_in[3];
    const float* w_fc  = (const float*)d_in[4];
    const float* b_fc  = (const float*)d_in[5];
    const float* w_fc1 = (const float*)d_in[6];
    const float* b_fc1 = (const float*)d_in[7];
    const float* w_ih  = (const float*)d_in[8];
    const float* w_hh  = (const float*)d_in[9];
    const float* b_ih  = (const float*)d_in[10];
    const float* b_hh  = (const float*)d_in[11];
    float* out = (float*)d_out;

    prep_kernel<<<148, 256>>>(w_fc, w_fc1, w_ih, w_hh, b_ih, b_hh);

    size_t smem_bytes = SM_TOT * sizeof(float);
    cudaFuncSetAttribute(speaker_kernel, cudaFuncAttributeMaxDynamicSharedMemorySize,
                         (int)smem_bytes);
    speaker_kernel<<<BB * CSZ, NTH, smem_bytes>>>(cosp, bank, mem_a, mem_b, b_fc, b_fc1, out);
}